// round 3
// baseline (speedup 1.0000x reference)
#include <cuda_runtime.h>
#include <math.h>

// Problem constants (fixed by the reference):
//   B=4, H=8, L=2048, DK=DV=32
#define LQ    2048
#define DKV   32
#define BQ    64
#define BK    64
#define NBH   32          // B*H
#define SCALE 0.17677669529663687f   // 1/sqrt(32)

#define QST_STRIDE (BQ + 4)   // 68 floats, keeps float4 alignment
#define KST_STRIDE (BK + 4)
#define PS_STRIDE  (BK + 4)

__global__ __launch_bounds__(256, 2)
void sdpa_fused_kernel(const float* __restrict__ Qg_,
                       const float* __restrict__ Kg_,
                       const float* __restrict__ Vg_,
                       const int* __restrict__ Mg_,
                       const float* __restrict__ Rg_,
                       float* __restrict__ ctx_out,
                       float* __restrict__ sc_out)
{
    const int qb  = blockIdx.x;     // q block index (0..31)
    const int bh  = blockIdx.y;     // batch*head   (0..31)
    const int tid = threadIdx.x;
    const int tx  = tid & 15;       // 0..15 : k / v dimension
    const int ty  = tid >> 4;       // 0..15 : q dimension

    __shared__ float Qst[DKV * QST_STRIDE];  // transposed Q tile [d][q]
    __shared__ float Kst[DKV * KST_STRIDE];  // transposed K tile [d][k]
    __shared__ float Vs [BK * DKV];          // V tile [k][v] row-major
    __shared__ float Ps [BQ * PS_STRIDE];    // probability tile [q][k]

    const float* Qg = Qg_ + (size_t)bh * LQ * DKV + (size_t)qb * BQ * DKV;
    const float* Kg = Kg_ + (size_t)bh * LQ * DKV;
    const float* Vg = Vg_ + (size_t)bh * LQ * DKV;
    const float* Rg = Rg_ + (size_t)bh * LQ * LQ + (size_t)qb * BQ * LQ;
    const int*   Mg = Mg_ + (size_t)bh * LQ * LQ + (size_t)qb * BQ * LQ;
    float* Sg = sc_out + (size_t)bh * LQ * LQ + (size_t)qb * BQ * LQ;

    // ---- load Q tile (64 x 32) transposed into Qst ----
    {
        const int r  = tid >> 2;          // 0..63  (q row)
        const int d0 = (tid & 3) * 8;     // 0,8,16,24
        float4 a = *reinterpret_cast<const float4*>(Qg + r * DKV + d0);
        float4 b = *reinterpret_cast<const float4*>(Qg + r * DKV + d0 + 4);
        Qst[(d0 + 0) * QST_STRIDE + r] = a.x;
        Qst[(d0 + 1) * QST_STRIDE + r] = a.y;
        Qst[(d0 + 2) * QST_STRIDE + r] = a.z;
        Qst[(d0 + 3) * QST_STRIDE + r] = a.w;
        Qst[(d0 + 4) * QST_STRIDE + r] = b.x;
        Qst[(d0 + 5) * QST_STRIDE + r] = b.y;
        Qst[(d0 + 6) * QST_STRIDE + r] = b.z;
        Qst[(d0 + 7) * QST_STRIDE + r] = b.w;
    }

    float m[4], l[4], acc[4][2];
#pragma unroll
    for (int i = 0; i < 4; ++i) {
        m[i] = -INFINITY; l[i] = 0.f;
        acc[i][0] = 0.f; acc[i][1] = 0.f;
    }

    for (int kb = 0; kb < LQ / BK; ++kb) {
        __syncthreads();   // previous-iteration readers of Kst/Vs are done

        // ---- load K tile transposed ----
        {
            const int r  = tid >> 2;
            const int d0 = (tid & 3) * 8;
            const float* kg = Kg + (size_t)kb * BK * DKV;
            float4 a = *reinterpret_cast<const float4*>(kg + r * DKV + d0);
            float4 b = *reinterpret_cast<const float4*>(kg + r * DKV + d0 + 4);
            Kst[(d0 + 0) * KST_STRIDE + r] = a.x;
            Kst[(d0 + 1) * KST_STRIDE + r] = a.y;
            Kst[(d0 + 2) * KST_STRIDE + r] = a.z;
            Kst[(d0 + 3) * KST_STRIDE + r] = a.w;
            Kst[(d0 + 4) * KST_STRIDE + r] = b.x;
            Kst[(d0 + 5) * KST_STRIDE + r] = b.y;
            Kst[(d0 + 6) * KST_STRIDE + r] = b.z;
            Kst[(d0 + 7) * KST_STRIDE + r] = b.w;
        }
        // ---- load V tile (straight copy, row-major [k][v]) ----
        {
            const float4* vg = reinterpret_cast<const float4*>(Vg + (size_t)kb * BK * DKV);
            float4* vs = reinterpret_cast<float4*>(Vs);
            vs[tid]       = vg[tid];
            vs[tid + 256] = vg[tid + 256];
        }
        __syncthreads();

        // ---- S = Q K^T  (each thread: 4 q-rows x 4 k-cols) ----
        float s[4][4];
#pragma unroll
        for (int i = 0; i < 4; ++i)
#pragma unroll
            for (int j = 0; j < 4; ++j) s[i][j] = 0.f;

#pragma unroll
        for (int d = 0; d < DKV; ++d) {
            float4 qf = *reinterpret_cast<const float4*>(&Qst[d * QST_STRIDE + ty * 4]);
            float4 kf = *reinterpret_cast<const float4*>(&Kst[d * KST_STRIDE + tx * 4]);
            const float qv[4] = {qf.x, qf.y, qf.z, qf.w};
            const float kv[4] = {kf.x, kf.y, kf.z, kf.w};
#pragma unroll
            for (int i = 0; i < 4; ++i)
#pragma unroll
                for (int j = 0; j < 4; ++j)
                    s[i][j] = fmaf(qv[i], kv[j], s[i][j]);
        }

        // ---- scale + residual + mask, write scores, online softmax ----
#pragma unroll
        for (int i = 0; i < 4; ++i) {
            const int qr = ty * 4 + i;
            const size_t row_off = (size_t)qr * LQ + (size_t)kb * BK + tx * 4;
            float4 rf = *reinterpret_cast<const float4*>(Rg + row_off);
            int4   mf = *reinterpret_cast<const int4*>(Mg + row_off);

            float sv[4];
            sv[0] = mf.x ? -1e9f : fmaf(s[i][0], SCALE, rf.x);
            sv[1] = mf.y ? -1e9f : fmaf(s[i][1], SCALE, rf.y);
            sv[2] = mf.z ? -1e9f : fmaf(s[i][2], SCALE, rf.z);
            sv[3] = mf.w ? -1e9f : fmaf(s[i][3], SCALE, rf.w);

            // write pre-softmax masked scores (second output)
            *reinterpret_cast<float4*>(Sg + row_off) = make_float4(sv[0], sv[1], sv[2], sv[3]);

            // row max across the tile (16 lanes share a q-row)
            float tmax = fmaxf(fmaxf(sv[0], sv[1]), fmaxf(sv[2], sv[3]));
#pragma unroll
            for (int off = 8; off > 0; off >>= 1)
                tmax = fmaxf(tmax, __shfl_xor_sync(0xffffffffu, tmax, off, 16));

            const float m_new = fmaxf(m[i], tmax);
            const float corr  = __expf(m[i] - m_new);   // 0 on first tile (m=-inf)
            m[i] = m_new;

            float p0 = __expf(sv[0] - m_new);
            float p1 = __expf(sv[1] - m_new);
            float p2 = __expf(sv[2] - m_new);
            float p3 = __expf(sv[3] - m_new);

            float psum = (p0 + p1) + (p2 + p3);
#pragma unroll
            for (int off = 8; off > 0; off >>= 1)
                psum += __shfl_xor_sync(0xffffffffu, psum, off, 16);

            l[i] = l[i] * corr + psum;
            acc[i][0] *= corr;
            acc[i][1] *= corr;

            *reinterpret_cast<float4*>(&Ps[qr * PS_STRIDE + tx * 4]) =
                make_float4(p0, p1, p2, p3);
        }
        __syncwarp();   // Ps rows are produced/consumed within the same half-warp

        // ---- PV: acc[q][v] += P[q][k] * V[k][v]  (each thread: 4 q x 2 v) ----
#pragma unroll
        for (int k4 = 0; k4 < BK; k4 += 4) {
            float4 pf[4];
#pragma unroll
            for (int i = 0; i < 4; ++i)
                pf[i] = *reinterpret_cast<const float4*>(&Ps[(ty * 4 + i) * PS_STRIDE + k4]);
#pragma unroll
            for (int c = 0; c < 4; ++c) {
                float2 vf = *reinterpret_cast<const float2*>(&Vs[(k4 + c) * DKV + tx * 2]);
                const float pc0 = reinterpret_cast<const float*>(&pf[0])[c];
                const float pc1 = reinterpret_cast<const float*>(&pf[1])[c];
                const float pc2 = reinterpret_cast<const float*>(&pf[2])[c];
                const float pc3 = reinterpret_cast<const float*>(&pf[3])[c];
                acc[0][0] = fmaf(pc0, vf.x, acc[0][0]);
                acc[0][1] = fmaf(pc0, vf.y, acc[0][1]);
                acc[1][0] = fmaf(pc1, vf.x, acc[1][0]);
                acc[1][1] = fmaf(pc1, vf.y, acc[1][1]);
                acc[2][0] = fmaf(pc2, vf.x, acc[2][0]);
                acc[2][1] = fmaf(pc2, vf.y, acc[2][1]);
                acc[3][0] = fmaf(pc3, vf.x, acc[3][0]);
                acc[3][1] = fmaf(pc3, vf.y, acc[3][1]);
            }
        }
    }

    // ---- epilogue: context = acc / l ----
    float* ctx = ctx_out + (size_t)bh * LQ * DKV + (size_t)qb * BQ * DKV;
#pragma unroll
    for (int i = 0; i < 4; ++i) {
        const float inv_l = 1.0f / l[i];
        const int qr = ty * 4 + i;
        *reinterpret_cast<float2*>(ctx + qr * DKV + tx * 2) =
            make_float2(acc[i][0] * inv_l, acc[i][1] * inv_l);
    }
}

extern "C" void kernel_launch(void* const* d_in, const int* in_sizes, int n_in,
                              void* d_out, int out_size)
{
    const float* Q    = (const float*)d_in[0];
    const float* K    = (const float*)d_in[1];
    const float* V    = (const float*)d_in[2];
    const int*   mask = (const int*)d_in[3];
    const float* res  = (const float*)d_in[4];

    float* ctx = (float*)d_out;                           // [B,H,L,DV]
    float* sc  = (float*)d_out + (size_t)NBH * LQ * DKV;  // [B,H,L,L]

    dim3 grid(LQ / BQ, NBH);
    sdpa_fused_kernel<<<grid, 256>>>(Q, K, V, mask, res, ctx, sc);
}